// round 1
// baseline (speedup 1.0000x reference)
#include <cuda_runtime.h>
#include <cuda_bf16.h>
#include <cstdint>

#define BB 64
#define NN 147
#define NSQ (NN*NN)          // 21609
#define NPIX (BB*NSQ)        // 1382976

// ---------------- scratch (device globals; no allocation allowed) ------------
__device__ float g_h1[(size_t)BB * NSQ * 16];   // conv1 out, NHWC  (88.5 MB)
__device__ float g_ahat[(size_t)BB * NSQ];      // A_hat then norm  [b][t][s]
__device__ float g_dinv[BB * NN];
__device__ float g_x0[(size_t)BB * NN * 32];    // node features
__device__ float g_xw[(size_t)BB * NN * 128];   // X @ W scratch
__device__ float g_fa[(size_t)BB * NN * 128];   // layer outputs ping
__device__ float g_fb[(size_t)BB * NN * 128];   // layer outputs pong

// ---------------- conv1: 3 -> 16, 3x3 SAME, ReLU, NHWC out -------------------
__global__ void conv1_kernel(const float* __restrict__ obs,
                             const float* __restrict__ w,
                             const float* __restrict__ bias) {
    __shared__ float sw[16*3*3*3];   // 432
    __shared__ float sb[16];
    for (int i = threadIdx.x; i < 432; i += blockDim.x) sw[i] = w[i];
    if (threadIdx.x < 16) sb[threadIdx.x] = bias[threadIdx.x];
    __syncthreads();

    int idx = blockIdx.x * blockDim.x + threadIdx.x;
    if (idx >= NPIX) return;
    int b  = idx / NSQ;
    int hw = idx % NSQ;
    int h  = hw / NN, wq = hw % NN;

    float acc[16];
#pragma unroll
    for (int o = 0; o < 16; o++) acc[o] = sb[o];

#pragma unroll
    for (int kh = 0; kh < 3; kh++) {
        int hi = h + kh - 1;
        if (hi < 0 || hi >= NN) continue;
#pragma unroll
        for (int kw = 0; kw < 3; kw++) {
            int wi = wq + kw - 1;
            if (wi < 0 || wi >= NN) continue;
            const float* p = obs + (((size_t)b*NN + hi)*NN + wi)*3;
            float i0 = p[0], i1 = p[1], i2 = p[2];
            int tap = kh*3 + kw;
#pragma unroll
            for (int o = 0; o < 16; o++) {
                acc[o] += i0 * sw[(o*3+0)*9 + tap]
                        + i1 * sw[(o*3+1)*9 + tap]
                        + i2 * sw[(o*3+2)*9 + tap];
            }
        }
    }
    float4* out = (float4*)(g_h1 + (size_t)idx * 16);
#pragma unroll
    for (int o = 0; o < 16; o++) acc[o] = fmaxf(acc[o], 0.0f);
    out[0] = make_float4(acc[0],  acc[1],  acc[2],  acc[3]);
    out[1] = make_float4(acc[4],  acc[5],  acc[6],  acc[7]);
    out[2] = make_float4(acc[8],  acc[9],  acc[10], acc[11]);
    out[3] = make_float4(acc[12], acc[13], acc[14], acc[15]);
}

// -------- conv2: 16 -> 32, 3x3 SAME, ReLU; fused ew/A_hat + diag extract -----
__global__ void conv2_kernel(const float* __restrict__ w,
                             const float* __restrict__ bias) {
    __shared__ float sw[9*16*32];    // [tap][ci][o], 18 KB
    __shared__ float sb[32];
    for (int i = threadIdx.x; i < 9*16*32; i += blockDim.x) {
        int tap = i / 512, r = i % 512, ci = r / 32, o = r % 32;
        sw[i] = w[(o*16 + ci)*9 + tap];
    }
    if (threadIdx.x < 32) sb[threadIdx.x] = bias[threadIdx.x];
    __syncthreads();

    int idx = blockIdx.x * blockDim.x + threadIdx.x;
    if (idx >= NPIX) return;
    int b  = idx / NSQ;
    int hw = idx % NSQ;
    int h  = hw / NN, wq = hw % NN;

    float acc[32];
#pragma unroll
    for (int o = 0; o < 32; o++) acc[o] = sb[o];

#pragma unroll
    for (int kh = 0; kh < 3; kh++) {
        int hi = h + kh - 1;
        if (hi < 0 || hi >= NN) continue;
#pragma unroll
        for (int kw = 0; kw < 3; kw++) {
            int wi = wq + kw - 1;
            if (wi < 0 || wi >= NN) continue;
            const float4* p = (const float4*)(g_h1 + (((size_t)b*NSQ) + hi*NN + wi)*16);
            float4 v0 = p[0], v1 = p[1], v2 = p[2], v3 = p[3];
            float in16[16] = {v0.x,v0.y,v0.z,v0.w, v1.x,v1.y,v1.z,v1.w,
                              v2.x,v2.y,v2.z,v2.w, v3.x,v3.y,v3.z,v3.w};
            int tapbase = (kh*3 + kw) * 512;
#pragma unroll
            for (int ci = 0; ci < 16; ci++) {
                float iv = in16[ci];
                const float* wp = &sw[tapbase + ci*32];
#pragma unroll
                for (int o = 0; o < 32; o++) acc[o] += iv * wp[o];
            }
        }
    }

    float sum = 0.0f;
#pragma unroll
    for (int o = 0; o < 32; o++) { acc[o] = fmaxf(acc[o], 0.0f); sum += acc[o]; }
    float ew = sum * (1.0f / 32.0f);
    // A_hat[b][t=wq][s=h] = ew[b,h,wq] + I
    g_ahat[(size_t)b*NSQ + (size_t)wq*NN + h] = ew + (h == wq ? 1.0f : 0.0f);
    if (h == wq) {
        float* xp = g_x0 + ((size_t)b*NN + h)*32;
#pragma unroll
        for (int o = 0; o < 32; o++) xp[o] = acc[o];
    }
}

// ---------------- degree / D^-1/2 --------------------------------------------
__global__ void deg_kernel() {
    int bt = blockIdx.x;                       // 0..B*N-1 : (b, t) row of A_hat
    const float* row = g_ahat + (size_t)bt * NN;
    int tid = threadIdx.x;
    float s = 0.0f;
    for (int i = tid; i < NN; i += 128) s += row[i];
#pragma unroll
    for (int o = 16; o > 0; o >>= 1) s += __shfl_xor_sync(0xffffffff, s, o);
    __shared__ float ws[4];
    if ((tid & 31) == 0) ws[tid >> 5] = s;
    __syncthreads();
    if (tid == 0) {
        float d = ws[0] + ws[1] + ws[2] + ws[3];
        g_dinv[bt] = d > 0.0f ? rsqrtf(d) : 0.0f;
    }
}

// ---------------- norm = dinv[t] * A_hat * dinv[s] (in place) ----------------
__global__ void norm_kernel() {
    int idx = blockIdx.x * blockDim.x + threadIdx.x;
    if (idx >= NPIX) return;
    int b = idx / NSQ, r = idx % NSQ;
    int t = r / NN, s = r % NN;
    g_ahat[idx] *= g_dinv[b*NN + t] * g_dinv[b*NN + s];
}

// ---------------- XW = X @ W  (block per node) -------------------------------
template<int FIN, int FOUT>
__global__ void xw_kernel(const float* __restrict__ X,
                          const float* __restrict__ W,
                          float* __restrict__ XW) {
    int bn = blockIdx.x;                // 0..B*N-1
    __shared__ float sx[FIN];
    if (threadIdx.x < FIN) sx[threadIdx.x] = X[(size_t)bn*FIN + threadIdx.x];
    __syncthreads();
    int f = threadIdx.x;                // FOUT threads
    float a = 0.0f;
#pragma unroll
    for (int i = 0; i < FIN; i++) a += sx[i] * W[i*FOUT + f];
    XW[(size_t)bn*FOUT + f] = a;
}

// ---------------- Y = relu(norm @ XW + b), tiled 21 rows ---------------------
template<int FOUT>
__global__ void agg_kernel(const float* __restrict__ XW,
                           const float* __restrict__ bias,
                           float* __restrict__ Y) {
    constexpr int TT  = 21;             // 147 = 7 * 21
    constexpr int SCH = 49;             // 147 = 3 * 49  (s-chunk)
    int blk = blockIdx.x;
    int b = blk / 7, t0 = (blk % 7) * TT;

    __shared__ float sxw[SCH * FOUT];   // <= 25 KB
    __shared__ float snorm[TT * NN];    // 12.3 KB

    const float* nb = g_ahat + (size_t)b*NSQ + (size_t)t0*NN;
    for (int i = threadIdx.x; i < TT*NN; i += FOUT) snorm[i] = nb[i];

    int f = threadIdx.x;
    float acc[TT];
#pragma unroll
    for (int r = 0; r < TT; r++) acc[r] = 0.0f;

    const float* xwb = XW + (size_t)b*NN*FOUT;
    for (int c = 0; c < 3; c++) {
        __syncthreads();
        for (int i = threadIdx.x; i < SCH*FOUT; i += FOUT)
            sxw[i] = xwb[(size_t)c*SCH*FOUT + i];
        __syncthreads();
        int sbase = c * SCH;
        for (int s = 0; s < SCH; s++) {
            float xv = sxw[s*FOUT + f];
#pragma unroll
            for (int r = 0; r < TT; r++) acc[r] += snorm[r*NN + sbase + s] * xv;
        }
    }
    float bv = bias[f];
#pragma unroll
    for (int r = 0; r < TT; r++)
        Y[((size_t)b*NN + t0 + r)*FOUT + f] = fmaxf(acc[r] + bv, 0.0f);
}

// ---------------- mean pool + policy head ------------------------------------
__global__ void head_kernel(const float* __restrict__ Y,
                            const float* __restrict__ pw,
                            const float* __restrict__ pb,
                            float* __restrict__ out) {
    int b = blockIdx.x;
    __shared__ float sp[128];
    int f = threadIdx.x;                // 128 threads
    float s = 0.0f;
    const float* yb = Y + (size_t)b*NN*128;
    for (int n = 0; n < NN; n++) s += yb[n*128 + f];
    sp[f] = s * (1.0f / NN);
    __syncthreads();
    if (f < 5) {
        float a = pb[f];
#pragma unroll
        for (int i = 0; i < 128; i++) a += sp[i] * pw[i*5 + f];
        out[b*5 + f] = a;
    }
}

// ---------------- launch -----------------------------------------------------
extern "C" void kernel_launch(void* const* d_in, const int* in_sizes, int n_in,
                              void* d_out, int out_size) {
    const float* obs      = (const float*)d_in[0];
    const float* conv1_w  = (const float*)d_in[1];
    const float* conv1_b  = (const float*)d_in[2];
    const float* conv2_w  = (const float*)d_in[3];
    const float* conv2_b  = (const float*)d_in[4];
    const float* gcn1_w   = (const float*)d_in[5];
    const float* gcn1_b   = (const float*)d_in[6];
    const float* gcn2_w   = (const float*)d_in[7];
    const float* gcn2_b   = (const float*)d_in[8];
    const float* gcn3_w   = (const float*)d_in[9];
    const float* gcn3_b   = (const float*)d_in[10];
    const float* policy_w = (const float*)d_in[11];
    const float* policy_b = (const float*)d_in[12];
    float* out = (float*)d_out;

    float *x0, *xw, *fa, *fb;
    cudaGetSymbolAddress((void**)&x0, g_x0);
    cudaGetSymbolAddress((void**)&xw, g_xw);
    cudaGetSymbolAddress((void**)&fa, g_fa);
    cudaGetSymbolAddress((void**)&fb, g_fb);

    int pixBlocks = (NPIX + 127) / 128;
    conv1_kernel<<<pixBlocks, 128>>>(obs, conv1_w, conv1_b);
    conv2_kernel<<<pixBlocks, 128>>>(conv2_w, conv2_b);
    deg_kernel<<<BB*NN, 128>>>();
    norm_kernel<<<(NPIX + 255) / 256, 256>>>();

    xw_kernel<32, 64><<<BB*NN, 64>>>(x0, gcn1_w, xw);
    agg_kernel<64><<<BB*7, 64>>>(xw, gcn1_b, fa);

    xw_kernel<64, 128><<<BB*NN, 128>>>(fa, gcn2_w, xw);
    agg_kernel<128><<<BB*7, 128>>>(xw, gcn2_b, fb);

    xw_kernel<128, 128><<<BB*NN, 128>>>(fb, gcn3_w, xw);
    agg_kernel<128><<<BB*7, 128>>>(xw, gcn3_b, fa);

    head_kernel<<<BB, 128>>>(fa, policy_w, policy_b, out);
}

// round 2
// speedup vs baseline: 2.0990x; 2.0990x over previous
#include <cuda_runtime.h>
#include <cuda_bf16.h>
#include <cstdint>

#define BB 64
#define NN 147
#define NSQ (NN*NN)          // 21609
#define NPIX (BB*NSQ)        // 1382976

// ---------------- scratch (device globals; no allocation allowed) ------------
__device__ float g_h1[(size_t)BB * NSQ * 16];   // conv1 out, NHWC  (88.5 MB)
__device__ float g_ahat[(size_t)BB * NSQ];      // A_hat then norm  [b][t][s]
__device__ float g_dinv[BB * NN];
__device__ float g_x0[(size_t)BB * NN * 32];    // node features
__device__ float g_xw[(size_t)BB * NN * 128];   // X @ W scratch
__device__ float g_fa[(size_t)BB * NN * 128];   // layer outputs ping
__device__ float g_fb[(size_t)BB * NN * 128];   // layer outputs pong

__device__ __forceinline__ uint32_t f2tf32(float f) {
    uint32_t r;
    asm("cvt.rna.tf32.f32 %0, %1;" : "=r"(r) : "f"(f));
    return r;
}

#define MMA_TF32(d, a0_, a1_, a2_, a3_, b0_, b1_)                              \
    asm volatile("mma.sync.aligned.m16n8k8.row.col.f32.tf32.tf32.f32 "         \
                 "{%0,%1,%2,%3}, {%4,%5,%6,%7}, {%8,%9}, {%0,%1,%2,%3};"       \
                 : "+f"((d)[0]), "+f"((d)[1]), "+f"((d)[2]), "+f"((d)[3])      \
                 : "r"(a0_), "r"(a1_), "r"(a2_), "r"(a3_), "r"(b0_), "r"(b1_))

// ---------------- conv1: 3 -> 16, 3x3 SAME, ReLU, NHWC out -------------------
__global__ void conv1_kernel(const float* __restrict__ obs,
                             const float* __restrict__ w,
                             const float* __restrict__ bias) {
    __shared__ float sw[9*3*16];     // [tap][ci][o] -> o contiguous (LDS.128)
    __shared__ float sb[16];
    for (int i = threadIdx.x; i < 432; i += blockDim.x) {
        int o = i / 27, r = i % 27, ci = r / 9, tap = r % 9;
        sw[tap*48 + ci*16 + o] = w[i];
    }
    if (threadIdx.x < 16) sb[threadIdx.x] = bias[threadIdx.x];
    __syncthreads();

    int idx = blockIdx.x * blockDim.x + threadIdx.x;
    if (idx >= NPIX) return;
    int b  = idx / NSQ;
    int hw = idx % NSQ;
    int h  = hw / NN, wq = hw % NN;

    float acc[16];
#pragma unroll
    for (int o = 0; o < 16; o++) acc[o] = sb[o];

#pragma unroll
    for (int kh = 0; kh < 3; kh++) {
        int hi = h + kh - 1;
        if (hi < 0 || hi >= NN) continue;
#pragma unroll
        for (int kw = 0; kw < 3; kw++) {
            int wi = wq + kw - 1;
            if (wi < 0 || wi >= NN) continue;
            const float* p = obs + (((size_t)b*NN + hi)*NN + wi)*3;
            float i0 = p[0], i1 = p[1], i2 = p[2];
            const float* wp = &sw[(kh*3 + kw)*48];
#pragma unroll
            for (int o = 0; o < 16; o++) {
                acc[o] += i0 * wp[o] + i1 * wp[16 + o] + i2 * wp[32 + o];
            }
        }
    }
    float4* out = (float4*)(g_h1 + (size_t)idx * 16);
#pragma unroll
    for (int o = 0; o < 16; o++) acc[o] = fmaxf(acc[o], 0.0f);
    out[0] = make_float4(acc[0],  acc[1],  acc[2],  acc[3]);
    out[1] = make_float4(acc[4],  acc[5],  acc[6],  acc[7]);
    out[2] = make_float4(acc[8],  acc[9],  acc[10], acc[11]);
    out[3] = make_float4(acc[12], acc[13], acc[14], acc[15]);
}

// -------- conv2 via tf32 mma implicit GEMM; fused ew/A_hat + diag ------------
// grid: (tiles_w=10, tiles_h=19, B). block = 128 threads = 8x16 pixel tile.
// K = 9 taps x 16 ci, N = 32 outputs.
#define CST 20                       // padded ci/k stride (bank-conflict-free)
#define SW_FLTS (9*32*CST)           // 5760
#define BUF_FLTS 4224                // max(patch 180*20=3600, out 128*33=4224)

__global__ void conv2_mma_kernel(const float* __restrict__ w,
                                 const float* __restrict__ bias) {
    __shared__ float s_all[SW_FLTS + BUF_FLTS];
    __shared__ float sb[32];
    uint32_t* sWu = (uint32_t*)s_all;
    uint32_t* sPu = (uint32_t*)(s_all + SW_FLTS);
    float*    sOut = s_all + SW_FLTS;

    int tid = threadIdx.x;
    int lane = tid & 31, warp = tid >> 5;
    int b   = blockIdx.z;
    int bw0 = blockIdx.x * 16;
    int bh0 = blockIdx.y * 8;

    // weights -> smem, layout [tap][o][k(pad CST)], tf32-rounded
    for (int i = tid; i < 9*32*16; i += 128) {
        int tap = i >> 9, r = i & 511, o = r >> 4, ci = r & 15;
        sWu[(tap*32 + o)*CST + ci] = f2tf32(w[(o*16 + ci)*9 + tap]);
    }
    if (tid < 32) sb[tid] = bias[tid];

    // stage 10x18 halo patch of h1 (16ch) -> smem, tf32-rounded
    const float* hb = g_h1 + (size_t)b * NSQ * 16;
    for (int i = tid; i < 180; i += 128) {
        int pr = i / 18, pc = i % 18;
        int hi = bh0 + pr - 1, wi = bw0 + pc - 1;
        uint32_t v[16];
        if (hi >= 0 && hi < NN && wi >= 0 && wi < NN) {
            const float4* p = (const float4*)(hb + ((size_t)hi*NN + wi)*16);
#pragma unroll
            for (int q = 0; q < 4; q++) {
                float4 f = p[q];
                v[q*4+0] = f2tf32(f.x); v[q*4+1] = f2tf32(f.y);
                v[q*4+2] = f2tf32(f.z); v[q*4+3] = f2tf32(f.w);
            }
        } else {
#pragma unroll
            for (int q = 0; q < 16; q++) v[q] = 0u;
        }
        uint4* dst = (uint4*)&sPu[i*CST];
#pragma unroll
        for (int q = 0; q < 4; q++)
            dst[q] = make_uint4(v[q*4], v[q*4+1], v[q*4+2], v[q*4+3]);
    }
    __syncthreads();

    float acc[2][4][4];
#pragma unroll
    for (int mt = 0; mt < 2; mt++)
#pragma unroll
        for (int nt = 0; nt < 4; nt++)
#pragma unroll
            for (int q = 0; q < 4; q++) acc[mt][nt][q] = 0.0f;

    int pw0 = lane >> 2, kk = lane & 3, og = lane >> 2;

#pragma unroll
    for (int th = 0; th < 3; th++) {
#pragma unroll
        for (int tw = 0; tw < 3; tw++) {
            int tap = th*3 + tw;
#pragma unroll
            for (int ks = 0; ks < 2; ks++) {
                int kb = ks * 8;
                uint32_t bf[4][2];
#pragma unroll
                for (int nt = 0; nt < 4; nt++) {
                    int o = nt*8 + og;
                    bf[nt][0] = sWu[(tap*32 + o)*CST + kb + kk];
                    bf[nt][1] = sWu[(tap*32 + o)*CST + kb + kk + 4];
                }
#pragma unroll
                for (int mt = 0; mt < 2; mt++) {
                    int ph = warp*2 + mt;
                    int rb = ((ph + th)*18 + tw)*CST + kb + kk;
                    uint32_t a0 = sPu[rb + pw0*CST];
                    uint32_t a1 = sPu[rb + (pw0+8)*CST];
                    uint32_t a2 = sPu[rb + pw0*CST + 4];
                    uint32_t a3 = sPu[rb + (pw0+8)*CST + 4];
#pragma unroll
                    for (int nt = 0; nt < 4; nt++)
                        MMA_TF32(acc[mt][nt], a0, a1, a2, a3,
                                 bf[nt][0], bf[nt][1]);
                }
            }
        }
    }

    __syncthreads();   // patch reads done; reuse buffer as sOut

    // scatter accums: bias + relu -> sOut[pixel][o], stride 33
    int m0 = warp * 32;
#pragma unroll
    for (int mt = 0; mt < 2; mt++) {
        int row0 = m0 + mt*16 + (lane >> 2);
#pragma unroll
        for (int nt = 0; nt < 4; nt++) {
            int col = nt*8 + (lane & 3)*2;
            sOut[row0*33 + col]       = fmaxf(acc[mt][nt][0] + sb[col],   0.0f);
            sOut[row0*33 + col + 1]   = fmaxf(acc[mt][nt][1] + sb[col+1], 0.0f);
            sOut[(row0+8)*33 + col]   = fmaxf(acc[mt][nt][2] + sb[col],   0.0f);
            sOut[(row0+8)*33 + col+1] = fmaxf(acc[mt][nt][3] + sb[col+1], 0.0f);
        }
    }
    __syncthreads();

    // per-pixel: channel mean -> A_hat (transposed, +I), diag -> x0
    {
        int ph = tid >> 4, pw = tid & 15;
        int h = bh0 + ph, wq = bw0 + pw;
        if (h < NN && wq < NN) {
            float s = 0.0f;
#pragma unroll
            for (int o = 0; o < 32; o++) s += sOut[tid*33 + o];
            float ew = s * (1.0f / 32.0f);
            g_ahat[(size_t)b*NSQ + (size_t)wq*NN + h] = ew + (h == wq ? 1.0f : 0.0f);
            if (h == wq) {
                float* xp = g_x0 + ((size_t)b*NN + h)*32;
#pragma unroll
                for (int o = 0; o < 32; o++) xp[o] = sOut[tid*33 + o];
            }
        }
    }
}

// ---------------- degree / D^-1/2 --------------------------------------------
__global__ void deg_kernel() {
    int bt = blockIdx.x;
    const float* row = g_ahat + (size_t)bt * NN;
    int tid = threadIdx.x;
    float s = 0.0f;
    for (int i = tid; i < NN; i += 128) s += row[i];
#pragma unroll
    for (int o = 16; o > 0; o >>= 1) s += __shfl_xor_sync(0xffffffff, s, o);
    __shared__ float ws[4];
    if ((tid & 31) == 0) ws[tid >> 5] = s;
    __syncthreads();
    if (tid == 0) {
        float d = ws[0] + ws[1] + ws[2] + ws[3];
        g_dinv[bt] = d > 0.0f ? rsqrtf(d) : 0.0f;
    }
}

// ---------------- norm = dinv[t] * A_hat * dinv[s] (in place) ----------------
__global__ void norm_kernel() {
    int idx = blockIdx.x * blockDim.x + threadIdx.x;
    if (idx >= NPIX) return;
    int b = idx / NSQ, r = idx % NSQ;
    int t = r / NN, s = r % NN;
    g_ahat[idx] *= g_dinv[b*NN + t] * g_dinv[b*NN + s];
}

// ---------------- XW = X @ W  (block per node) -------------------------------
template<int FIN, int FOUT>
__global__ void xw_kernel(const float* __restrict__ X,
                          const float* __restrict__ W,
                          float* __restrict__ XW) {
    int bn = blockIdx.x;
    __shared__ float sx[FIN];
    if (threadIdx.x < FIN) sx[threadIdx.x] = X[(size_t)bn*FIN + threadIdx.x];
    __syncthreads();
    int f = threadIdx.x;
    float a = 0.0f;
#pragma unroll
    for (int i = 0; i < FIN; i++) a += sx[i] * W[i*FOUT + f];
    XW[(size_t)bn*FOUT + f] = a;
}

// ---------------- Y = relu(norm @ XW + b), tiled 21 rows ---------------------
template<int FOUT>
__global__ void agg_kernel(const float* __restrict__ XW,
                           const float* __restrict__ bias,
                           float* __restrict__ Y) {
    constexpr int TT  = 21;
    constexpr int SCH = 49;
    int blk = blockIdx.x;
    int b = blk / 7, t0 = (blk % 7) * TT;

    __shared__ float sxw[SCH * FOUT];
    __shared__ float snorm[TT * NN];

    const float* nb = g_ahat + (size_t)b*NSQ + (size_t)t0*NN;
    for (int i = threadIdx.x; i < TT*NN; i += FOUT) snorm[i] = nb[i];

    int f = threadIdx.x;
    float acc[TT];
#pragma unroll
    for (int r = 0; r < TT; r++) acc[r] = 0.0f;

    const float* xwb = XW + (size_t)b*NN*FOUT;
    for (int c = 0; c < 3; c++) {
        __syncthreads();
        for (int i = threadIdx.x; i < SCH*FOUT; i += FOUT)
            sxw[i] = xwb[(size_t)c*SCH*FOUT + i];
        __syncthreads();
        int sbase = c * SCH;
        for (int s = 0; s < SCH; s++) {
            float xv = sxw[s*FOUT + f];
#pragma unroll
            for (int r = 0; r < TT; r++) acc[r] += snorm[r*NN + sbase + s] * xv;
        }
    }
    float bv = bias[f];
#pragma unroll
    for (int r = 0; r < TT; r++)
        Y[((size_t)b*NN + t0 + r)*FOUT + f] = fmaxf(acc[r] + bv, 0.0f);
}

// ---------------- mean pool + policy head ------------------------------------
__global__ void head_kernel(const float* __restrict__ Y,
                            const float* __restrict__ pw,
                            const float* __restrict__ pb,
                            float* __restrict__ out) {
    int b = blockIdx.x;
    __shared__ float sp[128];
    int f = threadIdx.x;
    float s = 0.0f;
    const float* yb = Y + (size_t)b*NN*128;
    for (int n = 0; n < NN; n++) s += yb[n*128 + f];
    sp[f] = s * (1.0f / NN);
    __syncthreads();
    if (f < 5) {
        float a = pb[f];
#pragma unroll
        for (int i = 0; i < 128; i++) a += sp[i] * pw[i*5 + f];
        out[b*5 + f] = a;
    }
}

// ---------------- launch -----------------------------------------------------
extern "C" void kernel_launch(void* const* d_in, const int* in_sizes, int n_in,
                              void* d_out, int out_size) {
    const float* obs      = (const float*)d_in[0];
    const float* conv1_w  = (const float*)d_in[1];
    const float* conv1_b  = (const float*)d_in[2];
    const float* conv2_w  = (const float*)d_in[3];
    const float* conv2_b  = (const float*)d_in[4];
    const float* gcn1_w   = (const float*)d_in[5];
    const float* gcn1_b   = (const float*)d_in[6];
    const float* gcn2_w   = (const float*)d_in[7];
    const float* gcn2_b   = (const float*)d_in[8];
    const float* gcn3_w   = (const float*)d_in[9];
    const float* gcn3_b   = (const float*)d_in[10];
    const float* policy_w = (const float*)d_in[11];
    const float* policy_b = (const float*)d_in[12];
    float* out = (float*)d_out;

    float *x0, *xw, *fa, *fb;
    cudaGetSymbolAddress((void**)&x0, g_x0);
    cudaGetSymbolAddress((void**)&xw, g_xw);
    cudaGetSymbolAddress((void**)&fa, g_fa);
    cudaGetSymbolAddress((void**)&fb, g_fb);

    int pixBlocks = (NPIX + 127) / 128;
    conv1_kernel<<<pixBlocks, 128>>>(obs, conv1_w, conv1_b);
    conv2_mma_kernel<<<dim3(10, 19, BB), 128>>>(conv2_w, conv2_b);
    deg_kernel<<<BB*NN, 128>>>();
    norm_kernel<<<(NPIX + 255) / 256, 256>>>();

    xw_kernel<32, 64><<<BB*NN, 64>>>(x0, gcn1_w, xw);
    agg_kernel<64><<<BB*7, 64>>>(xw, gcn1_b, fa);

    xw_kernel<64, 128><<<BB*NN, 128>>>(fa, gcn2_w, xw);
    agg_kernel<128><<<BB*7, 128>>>(xw, gcn2_b, fb);

    xw_kernel<128, 128><<<BB*NN, 128>>>(fb, gcn3_w, xw);
    agg_kernel<128><<<BB*7, 128>>>(xw, gcn3_b, fa);

    head_kernel<<<BB, 128>>>(fa, policy_w, policy_b, out);
}

// round 3
// speedup vs baseline: 2.1200x; 1.0100x over previous
#include <cuda_runtime.h>
#include <cuda_bf16.h>
#include <cstdint>

#define BB 64
#define NN 147
#define NSQ (NN*NN)          // 21609
#define NPIX (BB*NSQ)        // 1382976

// ---------------- scratch (device globals; no allocation allowed) ------------
__device__ float g_ahat[(size_t)BB * NSQ];      // A_hat (unnormalized) [b][t][s]
__device__ float g_dinv[BB * NN];
__device__ float g_x0[(size_t)BB * NN * 32];    // node features
__device__ float g_xw[(size_t)BB * NN * 128];   // X @ W scratch
__device__ float g_fa[(size_t)BB * NN * 128];   // layer outputs ping
__device__ float g_fb[(size_t)BB * NN * 128];   // layer outputs pong

__device__ __forceinline__ uint32_t f2tf32(float f) {
    uint32_t r;
    asm("cvt.rna.tf32.f32 %0, %1;" : "=r"(r) : "f"(f));
    return r;
}

#define MMA_TF32(d, a0_, a1_, a2_, a3_, b0_, b1_)                              \
    asm volatile("mma.sync.aligned.m16n8k8.row.col.f32.tf32.tf32.f32 "         \
                 "{%0,%1,%2,%3}, {%4,%5,%6,%7}, {%8,%9}, {%0,%1,%2,%3};"       \
                 : "+f"((d)[0]), "+f"((d)[1]), "+f"((d)[2]), "+f"((d)[3])      \
                 : "r"(a0_), "r"(a1_), "r"(a2_), "r"(a3_), "r"(b0_), "r"(b1_))

// ============ fused conv1(3->16) + conv2(16->32) + ew/A_hat/diag ==============
// grid: (tiles_w=10, tiles_h=19, B). block = 128 threads = 8x16 output tile.
#define CST 20                       // padded k stride (bank-conflict-free)
#define SW_FLTS (9*32*CST)           // 5760
#define BUF_FLTS 4224                // max(patch 180*20=3600, out 128*33=4224)

__global__ void conv_fused_kernel(const float* __restrict__ obs,
                                  const float* __restrict__ w1,
                                  const float* __restrict__ b1,
                                  const float* __restrict__ w2,
                                  const float* __restrict__ b2) {
    __shared__ float s_all[SW_FLTS + BUF_FLTS];
    __shared__ float sObs[12*20*3];      // obs halo patch [pr][pc][c]
    __shared__ float sw1[9*3*16];        // [tap][ci][o]
    __shared__ float sb1[16];
    __shared__ float sb2[32];
    uint32_t* sWu = (uint32_t*)s_all;
    uint32_t* sPu = (uint32_t*)(s_all + SW_FLTS);
    float*    sOut = s_all + SW_FLTS;

    int tid = threadIdx.x;
    int lane = tid & 31, warp = tid >> 5;
    int b   = blockIdx.z;
    int bw0 = blockIdx.x * 16;
    int bh0 = blockIdx.y * 8;

    // conv2 weights -> smem, layout [tap][o][k(pad CST)], tf32-rounded
    for (int i = tid; i < 9*32*16; i += 128) {
        int tap = i >> 9, r = i & 511, o = r >> 4, ci = r & 15;
        sWu[(tap*32 + o)*CST + ci] = f2tf32(w2[(o*16 + ci)*9 + tap]);
    }
    // conv1 weights [tap][ci][o]
    for (int i = tid; i < 432; i += 128) {
        int o = i / 27, r = i % 27, ci = r / 9, tap = r % 9;
        sw1[tap*48 + ci*16 + o] = w1[i];
    }
    if (tid < 16) sb1[tid] = b1[tid];
    if (tid < 32) sb2[tid] = b2[tid];

    // obs halo patch: rows bh0-2..bh0+9, cols bw0-2..bw0+17
    for (int i = tid; i < 720; i += 128) {
        int pix = i / 3, c = i % 3;
        int pr = pix / 20, pc = pix % 20;
        int hi = bh0 + pr - 2, wi = bw0 + pc - 2;
        sObs[i] = (hi >= 0 && hi < NN && wi >= 0 && wi < NN)
                ? obs[(((size_t)b*NN + hi)*NN + wi)*3 + c] : 0.0f;
    }
    __syncthreads();

    // conv1 for the 10x18 h1 patch -> tf32 into sPu
#pragma unroll
    for (int pp = 0; pp < 2; pp++) {
        int p = tid + pp*128;
        if (p < 180) {
            int pr1 = p / 18, pc1 = p % 18;
            int hi = bh0 + pr1 - 1, wi = bw0 + pc1 - 1;
            uint32_t v[16];
            if (hi >= 0 && hi < NN && wi >= 0 && wi < NN) {
                float acc[16];
#pragma unroll
                for (int o = 0; o < 16; o++) acc[o] = sb1[o];
#pragma unroll
                for (int kh = 0; kh < 3; kh++) {
#pragma unroll
                    for (int kw = 0; kw < 3; kw++) {
                        const float* ip = &sObs[((pr1+kh)*20 + pc1+kw)*3];
                        float i0 = ip[0], i1 = ip[1], i2 = ip[2];
                        const float* wp = &sw1[(kh*3 + kw)*48];
#pragma unroll
                        for (int o = 0; o < 16; o++)
                            acc[o] += i0*wp[o] + i1*wp[16+o] + i2*wp[32+o];
                    }
                }
#pragma unroll
                for (int o = 0; o < 16; o++) v[o] = f2tf32(fmaxf(acc[o], 0.0f));
            } else {
#pragma unroll
                for (int o = 0; o < 16; o++) v[o] = 0u;
            }
            uint4* dst = (uint4*)&sPu[p*CST];
#pragma unroll
            for (int q = 0; q < 4; q++)
                dst[q] = make_uint4(v[q*4], v[q*4+1], v[q*4+2], v[q*4+3]);
        }
    }
    __syncthreads();

    // conv2: tf32 MMA, K = 9 taps x 16 ci, M = 128 pixels, N = 32
    float acc[2][4][4];
#pragma unroll
    for (int mt = 0; mt < 2; mt++)
#pragma unroll
        for (int nt = 0; nt < 4; nt++)
#pragma unroll
            for (int q = 0; q < 4; q++) acc[mt][nt][q] = 0.0f;

    int pw0 = lane >> 2, kk = lane & 3, og = lane >> 2;

#pragma unroll
    for (int th = 0; th < 3; th++) {
#pragma unroll
        for (int tw = 0; tw < 3; tw++) {
            int tap = th*3 + tw;
#pragma unroll
            for (int ks = 0; ks < 2; ks++) {
                int kb = ks * 8;
                uint32_t bf[4][2];
#pragma unroll
                for (int nt = 0; nt < 4; nt++) {
                    int o = nt*8 + og;
                    bf[nt][0] = sWu[(tap*32 + o)*CST + kb + kk];
                    bf[nt][1] = sWu[(tap*32 + o)*CST + kb + kk + 4];
                }
#pragma unroll
                for (int mt = 0; mt < 2; mt++) {
                    int ph = warp*2 + mt;
                    int rb = ((ph + th)*18 + tw)*CST + kb + kk;
                    uint32_t a0 = sPu[rb + pw0*CST];
                    uint32_t a1 = sPu[rb + (pw0+8)*CST];
                    uint32_t a2 = sPu[rb + pw0*CST + 4];
                    uint32_t a3 = sPu[rb + (pw0+8)*CST + 4];
#pragma unroll
                    for (int nt = 0; nt < 4; nt++)
                        MMA_TF32(acc[mt][nt], a0, a1, a2, a3,
                                 bf[nt][0], bf[nt][1]);
                }
            }
        }
    }

    __syncthreads();   // patch reads done; reuse buffer as sOut

    int m0 = warp * 32;
#pragma unroll
    for (int mt = 0; mt < 2; mt++) {
        int row0 = m0 + mt*16 + (lane >> 2);
#pragma unroll
        for (int nt = 0; nt < 4; nt++) {
            int col = nt*8 + (lane & 3)*2;
            sOut[row0*33 + col]       = fmaxf(acc[mt][nt][0] + sb2[col],   0.0f);
            sOut[row0*33 + col + 1]   = fmaxf(acc[mt][nt][1] + sb2[col+1], 0.0f);
            sOut[(row0+8)*33 + col]   = fmaxf(acc[mt][nt][2] + sb2[col],   0.0f);
            sOut[(row0+8)*33 + col+1] = fmaxf(acc[mt][nt][3] + sb2[col+1], 0.0f);
        }
    }
    __syncthreads();

    // per-pixel: channel mean -> A_hat (transposed, +I), diag -> x0
    {
        int ph = tid >> 4, pw = tid & 15;
        int h = bh0 + ph, wq = bw0 + pw;
        if (h < NN && wq < NN) {
            float s = 0.0f;
#pragma unroll
            for (int o = 0; o < 32; o++) s += sOut[tid*33 + o];
            float ew = s * (1.0f / 32.0f);
            g_ahat[(size_t)b*NSQ + (size_t)wq*NN + h] = ew + (h == wq ? 1.0f : 0.0f);
            if (h == wq) {
                float* xp = g_x0 + ((size_t)b*NN + h)*32;
#pragma unroll
                for (int o = 0; o < 32; o++) xp[o] = sOut[tid*33 + o];
            }
        }
    }
}

// ---------------- degree / D^-1/2 --------------------------------------------
__global__ void deg_kernel() {
    int bt = blockIdx.x;
    const float* row = g_ahat + (size_t)bt * NN;
    int tid = threadIdx.x;
    float s = 0.0f;
    for (int i = tid; i < NN; i += 128) s += row[i];
#pragma unroll
    for (int o = 16; o > 0; o >>= 1) s += __shfl_xor_sync(0xffffffff, s, o);
    __shared__ float ws[4];
    if ((tid & 31) == 0) ws[tid >> 5] = s;
    __syncthreads();
    if (tid == 0) {
        float d = ws[0] + ws[1] + ws[2] + ws[3];
        g_dinv[bt] = d > 0.0f ? rsqrtf(d) : 0.0f;
    }
}

// ---------------- XW = X @ W  (21 nodes per block, W tiled via smem) ---------
template<int FIN, int FOUT>
__global__ void xw_kernel(const float* __restrict__ X,
                          const float* __restrict__ W,
                          float* __restrict__ XW) {
    constexpr int NB = 21;               // 9408 / 21 = 448 blocks
    constexpr int KT = 32;
    __shared__ float sX[NB*FIN];
    __shared__ float sW[KT*FOUT];
    int n0 = blockIdx.x * NB;
    int f = threadIdx.x;                 // blockDim = FOUT

    for (int i = f; i < NB*FIN; i += FOUT) sX[i] = X[(size_t)n0*FIN + i];

    float acc[NB];
#pragma unroll
    for (int n = 0; n < NB; n++) acc[n] = 0.0f;

    for (int kc = 0; kc < FIN; kc += KT) {
        __syncthreads();
        for (int i = f; i < KT*FOUT; i += FOUT) sW[i] = W[kc*FOUT + i];
        __syncthreads();
#pragma unroll
        for (int k = 0; k < KT; k++) {
            float wv = sW[k*FOUT + f];
#pragma unroll
            for (int n = 0; n < NB; n++) acc[n] += sX[n*FIN + kc + k] * wv;
        }
    }
#pragma unroll
    for (int n = 0; n < NB; n++) XW[(size_t)(n0+n)*FOUT + f] = acc[n];
}

// ------ Y = relu( (dinv A_hat dinv) @ XW + b ), norm folded into loads -------
template<int FOUT>
__global__ void agg_kernel(const float* __restrict__ XW,
                           const float* __restrict__ bias,
                           float* __restrict__ Y) {
    constexpr int TT  = 21;
    constexpr int SCH = 49;
    int blk = blockIdx.x;
    int b = blk / 7, t0 = (blk % 7) * TT;

    __shared__ float sxw[SCH * FOUT];
    __shared__ float snorm[TT * NN];
    __shared__ float sds[NN];

    int f = threadIdx.x;
    for (int i = f; i < NN; i += FOUT) sds[i] = g_dinv[b*NN + i];
    __syncthreads();

    const float* nb = g_ahat + (size_t)b*NSQ + (size_t)t0*NN;
    for (int i = f; i < TT*NN; i += FOUT) {
        int r = i / NN, s = i - r*NN;
        snorm[i] = nb[i] * sds[t0 + r] * sds[s];
    }

    float acc[TT];
#pragma unroll
    for (int r = 0; r < TT; r++) acc[r] = 0.0f;

    const float* xwb = XW + (size_t)b*NN*FOUT;
    for (int c = 0; c < 3; c++) {
        __syncthreads();
        for (int i = f; i < SCH*FOUT; i += FOUT)
            sxw[i] = xwb[(size_t)c*SCH*FOUT + i];
        __syncthreads();
        int sbase = c * SCH;
        for (int s = 0; s < SCH; s++) {
            float xv = sxw[s*FOUT + f];
#pragma unroll
            for (int r = 0; r < TT; r++) acc[r] += snorm[r*NN + sbase + s] * xv;
        }
    }
    float bv = bias[f];
#pragma unroll
    for (int r = 0; r < TT; r++)
        Y[((size_t)b*NN + t0 + r)*FOUT + f] = fmaxf(acc[r] + bv, 0.0f);
}

// ---------------- mean pool + policy head ------------------------------------
__global__ void head_kernel(const float* __restrict__ Y,
                            const float* __restrict__ pw,
                            const float* __restrict__ pb,
                            float* __restrict__ out) {
    int b = blockIdx.x;
    __shared__ float sp[128];
    int f = threadIdx.x;
    float s = 0.0f;
    const float* yb = Y + (size_t)b*NN*128;
    for (int n = 0; n < NN; n++) s += yb[n*128 + f];
    sp[f] = s * (1.0f / NN);
    __syncthreads();
    if (f < 5) {
        float a = pb[f];
#pragma unroll
        for (int i = 0; i < 128; i++) a += sp[i] * pw[i*5 + f];
        out[b*5 + f] = a;
    }
}

// ---------------- launch -----------------------------------------------------
extern "C" void kernel_launch(void* const* d_in, const int* in_sizes, int n_in,
                              void* d_out, int out_size) {
    const float* obs      = (const float*)d_in[0];
    const float* conv1_w  = (const float*)d_in[1];
    const float* conv1_b  = (const float*)d_in[2];
    const float* conv2_w  = (const float*)d_in[3];
    const float* conv2_b  = (const float*)d_in[4];
    const float* gcn1_w   = (const float*)d_in[5];
    const float* gcn1_b   = (const float*)d_in[6];
    const float* gcn2_w   = (const float*)d_in[7];
    const float* gcn2_b   = (const float*)d_in[8];
    const float* gcn3_w   = (const float*)d_in[9];
    const float* gcn3_b   = (const float*)d_in[10];
    const float* policy_w = (const float*)d_in[11];
    const float* policy_b = (const float*)d_in[12];
    float* out = (float*)d_out;

    float *x0, *xw, *fa, *fb;
    cudaGetSymbolAddress((void**)&x0, g_x0);
    cudaGetSymbolAddress((void**)&xw, g_xw);
    cudaGetSymbolAddress((void**)&fa, g_fa);
    cudaGetSymbolAddress((void**)&fb, g_fb);

    conv_fused_kernel<<<dim3(10, 19, BB), 128>>>(obs, conv1_w, conv1_b,
                                                 conv2_w, conv2_b);
    deg_kernel<<<BB*NN, 128>>>();

    xw_kernel<32, 64><<<448, 64>>>(x0, gcn1_w, xw);
    agg_kernel<64><<<BB*7, 64>>>(xw, gcn1_b, fa);

    xw_kernel<64, 128><<<448, 128>>>(fa, gcn2_w, xw);
    agg_kernel<128><<<BB*7, 128>>>(xw, gcn2_b, fb);

    xw_kernel<128, 128><<<448, 128>>>(fb, gcn3_w, xw);
    agg_kernel<128><<<BB*7, 128>>>(xw, gcn3_b, fa);

    head_kernel<<<BB, 128>>>(fa, policy_w, policy_b, out);
}

// round 4
// speedup vs baseline: 2.8624x; 1.3502x over previous
#include <cuda_runtime.h>
#include <cuda_bf16.h>
#include <cstdint>

#define BB 64
#define NN 147
#define NSQ (NN*NN)          // 21609
#define NPIX (BB*NSQ)        // 1382976

// ---------------- scratch (device globals; no allocation allowed) ------------
__device__ float g_ahat[(size_t)BB * NSQ];      // A_hat (unnormalized) [b][t][s]
__device__ float g_dinv[BB * NN];
__device__ float g_x0[(size_t)BB * NN * 32];    // node features
__device__ float g_xw[((size_t)BB * NN + 8) * 128]; // X @ W scratch (+8 pad rows)
__device__ float g_fa[(size_t)BB * NN * 128];   // layer outputs ping
__device__ float g_fb[(size_t)BB * NN * 128];   // layer outputs pong

__device__ __forceinline__ uint32_t f2tf32(float f) {
    uint32_t r;
    asm("cvt.rna.tf32.f32 %0, %1;" : "=r"(r) : "f"(f));
    return r;
}

#define MMA_TF32(d, a0_, a1_, a2_, a3_, b0_, b1_)                              \
    asm volatile("mma.sync.aligned.m16n8k8.row.col.f32.tf32.tf32.f32 "         \
                 "{%0,%1,%2,%3}, {%4,%5,%6,%7}, {%8,%9}, {%0,%1,%2,%3};"       \
                 : "+f"((d)[0]), "+f"((d)[1]), "+f"((d)[2]), "+f"((d)[3])      \
                 : "r"(a0_), "r"(a1_), "r"(a2_), "r"(a3_), "r"(b0_), "r"(b1_))

// ============ fused conv1(3->16) + conv2(16->32) + ew/A_hat/diag ==============
#define CST 20
#define SW_FLTS (9*32*CST)           // 5760
#define BUF_FLTS 4224

__global__ void conv_fused_kernel(const float* __restrict__ obs,
                                  const float* __restrict__ w1,
                                  const float* __restrict__ b1,
                                  const float* __restrict__ w2,
                                  const float* __restrict__ b2) {
    __shared__ float s_all[SW_FLTS + BUF_FLTS];
    __shared__ float sObs[12*20*3];
    __shared__ float sw1[9*3*16];
    __shared__ float sb1[16];
    __shared__ float sb2[32];
    uint32_t* sWu = (uint32_t*)s_all;
    uint32_t* sPu = (uint32_t*)(s_all + SW_FLTS);
    float*    sOut = s_all + SW_FLTS;

    int tid = threadIdx.x;
    int lane = tid & 31, warp = tid >> 5;
    int b   = blockIdx.z;
    int bw0 = blockIdx.x * 16;
    int bh0 = blockIdx.y * 8;

    for (int i = tid; i < 9*32*16; i += 128) {
        int tap = i >> 9, r = i & 511, o = r >> 4, ci = r & 15;
        sWu[(tap*32 + o)*CST + ci] = f2tf32(w2[(o*16 + ci)*9 + tap]);
    }
    for (int i = tid; i < 432; i += 128) {
        int o = i / 27, r = i % 27, ci = r / 9, tap = r % 9;
        sw1[tap*48 + ci*16 + o] = w1[i];
    }
    if (tid < 16) sb1[tid] = b1[tid];
    if (tid < 32) sb2[tid] = b2[tid];

    for (int i = tid; i < 720; i += 128) {
        int pix = i / 3, c = i % 3;
        int pr = pix / 20, pc = pix % 20;
        int hi = bh0 + pr - 2, wi = bw0 + pc - 2;
        sObs[i] = (hi >= 0 && hi < NN && wi >= 0 && wi < NN)
                ? obs[(((size_t)b*NN + hi)*NN + wi)*3 + c] : 0.0f;
    }
    __syncthreads();

#pragma unroll
    for (int pp = 0; pp < 2; pp++) {
        int p = tid + pp*128;
        if (p < 180) {
            int pr1 = p / 18, pc1 = p % 18;
            int hi = bh0 + pr1 - 1, wi = bw0 + pc1 - 1;
            uint32_t v[16];
            if (hi >= 0 && hi < NN && wi >= 0 && wi < NN) {
                float acc[16];
#pragma unroll
                for (int o = 0; o < 16; o++) acc[o] = sb1[o];
#pragma unroll
                for (int kh = 0; kh < 3; kh++) {
#pragma unroll
                    for (int kw = 0; kw < 3; kw++) {
                        const float* ip = &sObs[((pr1+kh)*20 + pc1+kw)*3];
                        float i0 = ip[0], i1 = ip[1], i2 = ip[2];
                        const float* wp = &sw1[(kh*3 + kw)*48];
#pragma unroll
                        for (int o = 0; o < 16; o++)
                            acc[o] += i0*wp[o] + i1*wp[16+o] + i2*wp[32+o];
                    }
                }
#pragma unroll
                for (int o = 0; o < 16; o++) v[o] = f2tf32(fmaxf(acc[o], 0.0f));
            } else {
#pragma unroll
                for (int o = 0; o < 16; o++) v[o] = 0u;
            }
            uint4* dst = (uint4*)&sPu[p*CST];
#pragma unroll
            for (int q = 0; q < 4; q++)
                dst[q] = make_uint4(v[q*4], v[q*4+1], v[q*4+2], v[q*4+3]);
        }
    }
    __syncthreads();

    float acc[2][4][4];
#pragma unroll
    for (int mt = 0; mt < 2; mt++)
#pragma unroll
        for (int nt = 0; nt < 4; nt++)
#pragma unroll
            for (int q = 0; q < 4; q++) acc[mt][nt][q] = 0.0f;

    int pw0 = lane >> 2, kk = lane & 3, og = lane >> 2;

#pragma unroll
    for (int th = 0; th < 3; th++) {
#pragma unroll
        for (int tw = 0; tw < 3; tw++) {
            int tap = th*3 + tw;
#pragma unroll
            for (int ks = 0; ks < 2; ks++) {
                int kb = ks * 8;
                uint32_t bf[4][2];
#pragma unroll
                for (int nt = 0; nt < 4; nt++) {
                    int o = nt*8 + og;
                    bf[nt][0] = sWu[(tap*32 + o)*CST + kb + kk];
                    bf[nt][1] = sWu[(tap*32 + o)*CST + kb + kk + 4];
                }
#pragma unroll
                for (int mt = 0; mt < 2; mt++) {
                    int ph = warp*2 + mt;
                    int rb = ((ph + th)*18 + tw)*CST + kb + kk;
                    uint32_t a0 = sPu[rb + pw0*CST];
                    uint32_t a1 = sPu[rb + (pw0+8)*CST];
                    uint32_t a2 = sPu[rb + pw0*CST + 4];
                    uint32_t a3 = sPu[rb + (pw0+8)*CST + 4];
#pragma unroll
                    for (int nt = 0; nt < 4; nt++)
                        MMA_TF32(acc[mt][nt], a0, a1, a2, a3,
                                 bf[nt][0], bf[nt][1]);
                }
            }
        }
    }

    __syncthreads();

    int m0 = warp * 32;
#pragma unroll
    for (int mt = 0; mt < 2; mt++) {
        int row0 = m0 + mt*16 + (lane >> 2);
#pragma unroll
        for (int nt = 0; nt < 4; nt++) {
            int col = nt*8 + (lane & 3)*2;
            sOut[row0*33 + col]       = fmaxf(acc[mt][nt][0] + sb2[col],   0.0f);
            sOut[row0*33 + col + 1]   = fmaxf(acc[mt][nt][1] + sb2[col+1], 0.0f);
            sOut[(row0+8)*33 + col]   = fmaxf(acc[mt][nt][2] + sb2[col],   0.0f);
            sOut[(row0+8)*33 + col+1] = fmaxf(acc[mt][nt][3] + sb2[col+1], 0.0f);
        }
    }
    __syncthreads();

    {
        int ph = tid >> 4, pw = tid & 15;
        int h = bh0 + ph, wq = bw0 + pw;
        if (h < NN && wq < NN) {
            float s = 0.0f;
#pragma unroll
            for (int o = 0; o < 32; o++) s += sOut[tid*33 + o];
            float ew = s * (1.0f / 32.0f);
            g_ahat[(size_t)b*NSQ + (size_t)wq*NN + h] = ew + (h == wq ? 1.0f : 0.0f);
            if (h == wq) {
                float* xp = g_x0 + ((size_t)b*NN + h)*32;
#pragma unroll
                for (int o = 0; o < 32; o++) xp[o] = sOut[tid*33 + o];
            }
        }
    }
}

// ---------------- degree / D^-1/2 --------------------------------------------
__global__ void deg_kernel() {
    int bt = blockIdx.x;
    const float* row = g_ahat + (size_t)bt * NN;
    int tid = threadIdx.x;
    float s = 0.0f;
    for (int i = tid; i < NN; i += 128) s += row[i];
#pragma unroll
    for (int o = 16; o > 0; o >>= 1) s += __shfl_xor_sync(0xffffffff, s, o);
    __shared__ float ws[4];
    if ((tid & 31) == 0) ws[tid >> 5] = s;
    __syncthreads();
    if (tid == 0) {
        float d = ws[0] + ws[1] + ws[2] + ws[3];
        g_dinv[bt] = d > 0.0f ? rsqrtf(d) : 0.0f;
    }
}

// ------------- XW = X @ W via tf32 MMA.  M=9408, K=FIN, N=FOUT ---------------
// grid 147 blocks x 128 threads; warp handles 16 rows x FOUT cols.
template<int FIN, int FOUT>
__global__ void xw_mma_kernel(const float* __restrict__ X,
                              const float* __restrict__ W,
                              float* __restrict__ XW) {
    constexpr int NT = FOUT / 8;
    int lane = threadIdx.x & 31, warp = threadIdx.x >> 5;
    int m0 = blockIdx.x * 64 + warp * 16;
    int row = lane >> 2, kq = lane & 3;

    float acc[NT][4];
#pragma unroll
    for (int nt = 0; nt < NT; nt++)
#pragma unroll
        for (int q = 0; q < 4; q++) acc[nt][q] = 0.0f;

    const float* xr0 = X + (size_t)(m0 + row) * FIN;
    const float* xr1 = X + (size_t)(m0 + row + 8) * FIN;

#pragma unroll
    for (int ks = 0; ks < FIN/8; ks++) {
        int k0 = ks*8;
        uint32_t a0 = f2tf32(__ldg(xr0 + k0 + kq));
        uint32_t a1 = f2tf32(__ldg(xr1 + k0 + kq));
        uint32_t a2 = f2tf32(__ldg(xr0 + k0 + kq + 4));
        uint32_t a3 = f2tf32(__ldg(xr1 + k0 + kq + 4));
#pragma unroll
        for (int nt = 0; nt < NT; nt++) {
            int n = nt*8 + row;
            uint32_t b0 = f2tf32(__ldg(W + (size_t)(k0 + kq)*FOUT + n));
            uint32_t b1 = f2tf32(__ldg(W + (size_t)(k0 + kq + 4)*FOUT + n));
            MMA_TF32(acc[nt], a0, a1, a2, a3, b0, b1);
        }
    }

#pragma unroll
    for (int nt = 0; nt < NT; nt++) {
        int col = nt*8 + (lane & 3)*2;
        float2* p0 = (float2*)(XW + (size_t)(m0 + row)     * FOUT + col);
        float2* p1 = (float2*)(XW + (size_t)(m0 + row + 8) * FOUT + col);
        *p0 = make_float2(acc[nt][0], acc[nt][1]);
        *p1 = make_float2(acc[nt][2], acc[nt][3]);
    }
}

// ---- Y = relu( (dinv A_hat dinv) @ XW + b ) via tf32 MMA --------------------
// grid (10 mtiles, BB) x 128 threads. snorm tile 16x156 (tf32, dinv folded).
#define AST 156
template<int FOUT>
__global__ void agg_mma_kernel(const float* __restrict__ XW,
                               const float* __restrict__ bias,
                               float* __restrict__ Y) {
    constexpr int NTW = FOUT / 32;       // n-subtiles per warp
    __shared__ uint32_t sA[16 * AST];    // ~10 KB
    __shared__ float sds[160];

    int tid = threadIdx.x;
    int lane = tid & 31, warp = tid >> 5;
    int b = blockIdx.y, t0 = blockIdx.x * 16;

    for (int i = tid; i < 160; i += 128)
        sds[i] = (i < NN) ? g_dinv[b*NN + i] : 0.0f;
    __syncthreads();

    const float* ab = g_ahat + (size_t)b * NSQ;
    for (int i = tid; i < 16*AST; i += 128) {
        int r = i / AST, s = i - r*AST;
        int t = t0 + r;
        float v = 0.0f;
        if (t < NN && s < NN) v = ab[(size_t)t*NN + s] * sds[t] * sds[s];
        sA[i] = f2tf32(v);
    }
    __syncthreads();

    float acc[NTW][4];
#pragma unroll
    for (int nt = 0; nt < NTW; nt++)
#pragma unroll
        for (int q = 0; q < 4; q++) acc[nt][q] = 0.0f;

    int row = lane >> 2, kq = lane & 3;
    int wn0 = warp * (FOUT/4);
    const float* xwb = XW + (size_t)b * NN * FOUT;

#pragma unroll
    for (int ks = 0; ks < 19; ks++) {        // K = 152 (padded)
        int k0 = ks*8;
        uint32_t a0 = sA[row*AST + k0 + kq];
        uint32_t a1 = sA[(row+8)*AST + k0 + kq];
        uint32_t a2 = sA[row*AST + k0 + kq + 4];
        uint32_t a3 = sA[(row+8)*AST + k0 + kq + 4];
#pragma unroll
        for (int nt = 0; nt < NTW; nt++) {
            int n = wn0 + nt*8 + row;
            uint32_t b0 = f2tf32(__ldg(xwb + (size_t)(k0 + kq)*FOUT + n));
            uint32_t b1 = f2tf32(__ldg(xwb + (size_t)(k0 + kq + 4)*FOUT + n));
            MMA_TF32(acc[nt], a0, a1, a2, a3, b0, b1);
        }
    }

    int r0 = t0 + row, r1 = t0 + row + 8;
#pragma unroll
    for (int nt = 0; nt < NTW; nt++) {
        int col = wn0 + nt*8 + (lane & 3)*2;
        float bv0 = __ldg(bias + col), bv1 = __ldg(bias + col + 1);
        if (r0 < NN) {
            float2* p = (float2*)(Y + (size_t)(b*NN + r0)*FOUT + col);
            *p = make_float2(fmaxf(acc[nt][0] + bv0, 0.0f),
                             fmaxf(acc[nt][1] + bv1, 0.0f));
        }
        if (r1 < NN) {
            float2* p = (float2*)(Y + (size_t)(b*NN + r1)*FOUT + col);
            *p = make_float2(fmaxf(acc[nt][2] + bv0, 0.0f),
                             fmaxf(acc[nt][3] + bv1, 0.0f));
        }
    }
}

// ---------------- mean pool + policy head ------------------------------------
__global__ void head_kernel(const float* __restrict__ Y,
                            const float* __restrict__ pw,
                            const float* __restrict__ pb,
                            float* __restrict__ out) {
    int b = blockIdx.x;
    __shared__ float sp[128];
    int f = threadIdx.x;
    float s = 0.0f;
    const float* yb = Y + (size_t)b*NN*128;
    for (int n = 0; n < NN; n++) s += yb[n*128 + f];
    sp[f] = s * (1.0f / NN);
    __syncthreads();
    if (f < 5) {
        float a = pb[f];
#pragma unroll
        for (int i = 0; i < 128; i++) a += sp[i] * pw[i*5 + f];
        out[b*5 + f] = a;
    }
}

// ---------------- launch -----------------------------------------------------
extern "C" void kernel_launch(void* const* d_in, const int* in_sizes, int n_in,
                              void* d_out, int out_size) {
    const float* obs      = (const float*)d_in[0];
    const float* conv1_w  = (const float*)d_in[1];
    const float* conv1_b  = (const float*)d_in[2];
    const float* conv2_w  = (const float*)d_in[3];
    const float* conv2_b  = (const float*)d_in[4];
    const float* gcn1_w   = (const float*)d_in[5];
    const float* gcn1_b   = (const float*)d_in[6];
    const float* gcn2_w   = (const float*)d_in[7];
    const float* gcn2_b   = (const float*)d_in[8];
    const float* gcn3_w   = (const float*)d_in[9];
    const float* gcn3_b   = (const float*)d_in[10];
    const float* policy_w = (const float*)d_in[11];
    const float* policy_b = (const float*)d_in[12];
    float* out = (float*)d_out;

    float *x0, *xw, *fa, *fb;
    cudaGetSymbolAddress((void**)&x0, g_x0);
    cudaGetSymbolAddress((void**)&xw, g_xw);
    cudaGetSymbolAddress((void**)&fa, g_fa);
    cudaGetSymbolAddress((void**)&fb, g_fb);

    conv_fused_kernel<<<dim3(10, 19, BB), 128>>>(obs, conv1_w, conv1_b,
                                                 conv2_w, conv2_b);
    deg_kernel<<<BB*NN, 128>>>();

    xw_mma_kernel<32, 64><<<147, 128>>>(x0, gcn1_w, xw);
    agg_mma_kernel<64><<<dim3(10, BB), 128>>>(xw, gcn1_b, fa);

    xw_mma_kernel<64, 128><<<147, 128>>>(fa, gcn2_w, xw);
    agg_mma_kernel<128><<<dim3(10, BB), 128>>>(xw, gcn2_b, fb);

    xw_mma_kernel<128, 128><<<147, 128>>>(fb, gcn3_w, xw);
    agg_mma_kernel<128><<<dim3(10, BB), 128>>>(xw, gcn3_b, fa);

    head_kernel<<<BB, 128>>>(fa, policy_w, policy_b, out);
}

// round 5
// speedup vs baseline: 3.5923x; 1.2550x over previous
#include <cuda_runtime.h>
#include <cuda_bf16.h>
#include <cstdint>

#define BB 64
#define NN 147
#define NSQ (NN*NN)          // 21609
#define NPIX (BB*NSQ)        // 1382976

// ---------------- scratch (device globals; no allocation allowed) ------------
__device__ float g_ahat[(size_t)BB * NSQ];      // A_hat (unnormalized) [b][t][s]
__device__ float g_dinv[BB * NN];
__device__ float g_x0[(size_t)BB * NN * 32];    // node features
__device__ float g_xw[((size_t)BB * NN + 8) * 128]; // X @ W scratch (+8 pad rows)
__device__ float g_fa[(size_t)BB * NN * 128];   // layer outputs ping
__device__ float g_fb[(size_t)BB * NN * 128];   // layer outputs pong

#define CST 20
#define SW_FLTS (9*32*CST)           // 5760
#define BUF_FLTS 4224

__device__ uint32_t g_w2t[SW_FLTS];  // conv2 weights tf32, [tap*32+o]*CST+ci, pad=0
__device__ uint32_t g_w1t[32*16];    // conv1 weights tf32, [k=tap*3+c][o], k>=27 -> 0

__device__ __forceinline__ uint32_t f2tf32(float f) {
    uint32_t r;
    asm("cvt.rna.tf32.f32 %0, %1;" : "=r"(r) : "f"(f));
    return r;
}

#define MMA_TF32(d, a0_, a1_, a2_, a3_, b0_, b1_)                              \
    asm volatile("mma.sync.aligned.m16n8k8.row.col.f32.tf32.tf32.f32 "         \
                 "{%0,%1,%2,%3}, {%4,%5,%6,%7}, {%8,%9}, {%0,%1,%2,%3};"       \
                 : "+f"((d)[0]), "+f"((d)[1]), "+f"((d)[2]), "+f"((d)[3])      \
                 : "r"(a0_), "r"(a1_), "r"(a2_), "r"(a3_), "r"(b0_), "r"(b1_))

// ---------------- one-time weight relayout/convert ---------------------------
__global__ void prep_kernel(const float* __restrict__ w1,
                            const float* __restrict__ w2) {
    int i = blockIdx.x * 256 + threadIdx.x;
    if (i < SW_FLTS) {
        int rowr = i / CST, ci = i - rowr * CST;
        int tap = rowr >> 5, o = rowr & 31;
        g_w2t[i] = (ci < 16) ? f2tf32(w2[(o*16 + ci)*9 + tap]) : 0u;
    }
    if (i < 512) {
        int k = i >> 4, o = i & 15;
        uint32_t v = 0u;
        if (k < 27) {
            int tap = (k*11) >> 5, c = k - 3*tap;
            int kh = (tap*11) >> 5, kw = tap - 3*kh;
            v = f2tf32(w1[((o*3 + c)*3 + kh)*3 + kw]);   // OIHW
        }
        g_w1t[i] = v;
    }
}

// ====== fused conv1(3->16, MMA) + conv2(16->32, MMA) + ew/A_hat/diag =========
// grid: (10, 19, B). block = 128 threads = 8x16 output tile.
__global__ void conv_fused_kernel(const float* __restrict__ obs,
                                  const float* __restrict__ b1,
                                  const float* __restrict__ b2) {
    __shared__ float s_all[SW_FLTS + BUF_FLTS];
    __shared__ uint32_t sObs32[800];     // 12x20x3 tf32 patch + zero pad
    __shared__ uint32_t sW1u[512];       // [k=32][o=16]
    __shared__ float sb1[16];
    __shared__ float sb2[32];
    uint32_t* sWu = (uint32_t*)s_all;
    uint32_t* sPu = (uint32_t*)(s_all + SW_FLTS);
    float*    sOut = s_all + SW_FLTS;

    int tid = threadIdx.x;
    int lane = tid & 31, warp = tid >> 5;
    int b   = blockIdx.z;
    int bw0 = blockIdx.x * 16;
    int bh0 = blockIdx.y * 8;

    // stage weights (precomputed tf32): pure coalesced copies
    {
        uint4* dst = (uint4*)sWu;
        const uint4* src = (const uint4*)g_w2t;
        for (int i = tid; i < SW_FLTS/4; i += 128) dst[i] = src[i];
        ((uint4*)sW1u)[tid] = ((const uint4*)g_w1t)[tid];   // 512 = 128*4
    }
    if (tid < 16) sb1[tid] = b1[tid];
    if (tid < 32) sb2[tid] = b2[tid];
    if (tid < 80) sObs32[720 + tid] = 0u;    // pad region must be finite

    // obs halo patch (tf32): rows bh0-2..bh0+9, cols bw0-2..bw0+17
    for (int i = tid; i < 720; i += 128) {
        int pix = i / 3, c = i - pix*3;
        int pr = pix / 20, pc = pix - pr*20;
        int hi = bh0 + pr - 2, wi = bw0 + pc - 2;
        float v = (hi >= 0 && hi < NN && wi >= 0 && wi < NN)
                ? obs[(((size_t)b*NN + hi)*NN + wi)*3 + c] : 0.0f;
        sObs32[i] = f2tf32(v);
    }
    __syncthreads();

    // ---------- conv1 via MMA: A = 192 pixels x K32 (im2col), B = w1 --------
    {
        int row = lane >> 2, kq = lane & 3;
        int offA[4][2];
#pragma unroll
        for (int ks = 0; ks < 4; ks++) {
#pragma unroll
            for (int hh = 0; hh < 2; hh++) {
                int k = ks*8 + kq + hh*4;
                int tap = (k*11) >> 5, c = k - 3*tap;
                int kh = (tap*11) >> 5, kw = tap - 3*kh;
                offA[ks][hh] = kh*60 + kw*3 + c;
            }
        }

        float accP[3][2][4];
#pragma unroll
        for (int mt = 0; mt < 3; mt++)
#pragma unroll
            for (int nt = 0; nt < 2; nt++)
#pragma unroll
                for (int q = 0; q < 4; q++) accP[mt][nt][q] = 0.0f;

#pragma unroll
        for (int mt = 0; mt < 3; mt++) {
            int p1 = warp*48 + mt*16 + row;
            int p2 = p1 + 8;
            int p1c = min(p1, 179), p2c = min(p2, 179);
            int pr1 = p1c / 18, pr2 = p2c / 18;
            int bp1 = pr1*60 + (p1c - pr1*18)*3;
            int bp2 = pr2*60 + (p2c - pr2*18)*3;
#pragma unroll
            for (int ks = 0; ks < 4; ks++) {
                uint32_t a0 = sObs32[bp1 + offA[ks][0]];
                uint32_t a1 = sObs32[bp2 + offA[ks][0]];
                uint32_t a2 = sObs32[bp1 + offA[ks][1]];
                uint32_t a3 = sObs32[bp2 + offA[ks][1]];
#pragma unroll
                for (int nt = 0; nt < 2; nt++) {
                    int n = nt*8 + row;
                    uint32_t b0 = sW1u[(ks*8 + kq)*16 + n];
                    uint32_t b1v = sW1u[(ks*8 + kq + 4)*16 + n];
                    MMA_TF32(accP[mt][nt], a0, a1, a2, a3, b0, b1v);
                }
            }
        }

        // relu+bias -> tf32 -> sPu[p*CST + ch]
        int colq = (lane & 3)*2;
#pragma unroll
        for (int mt = 0; mt < 3; mt++) {
            int p1 = warp*48 + mt*16 + row, p2 = p1 + 8;
#pragma unroll
            for (int nt = 0; nt < 2; nt++) {
                int ch = nt*8 + colq;
                if (p1 < 180) {
                    uint2 v;
                    v.x = f2tf32(fmaxf(accP[mt][nt][0] + sb1[ch],   0.0f));
                    v.y = f2tf32(fmaxf(accP[mt][nt][1] + sb1[ch+1], 0.0f));
                    *(uint2*)&sPu[p1*CST + ch] = v;
                }
                if (p2 < 180) {
                    uint2 v;
                    v.x = f2tf32(fmaxf(accP[mt][nt][2] + sb1[ch],   0.0f));
                    v.y = f2tf32(fmaxf(accP[mt][nt][3] + sb1[ch+1], 0.0f));
                    *(uint2*)&sPu[p2*CST + ch] = v;
                }
            }
        }
    }
    __syncthreads();

    // ---------- conv2 via MMA: K = 9 taps x 16 ci, M = 128 px, N = 32 -------
    float acc[2][4][4];
#pragma unroll
    for (int mt = 0; mt < 2; mt++)
#pragma unroll
        for (int nt = 0; nt < 4; nt++)
#pragma unroll
            for (int q = 0; q < 4; q++) acc[mt][nt][q] = 0.0f;

    int pw0 = lane >> 2, kk = lane & 3, og = lane >> 2;

#pragma unroll
    for (int th = 0; th < 3; th++) {
#pragma unroll
        for (int tw = 0; tw < 3; tw++) {
            int tap = th*3 + tw;
#pragma unroll
            for (int ks = 0; ks < 2; ks++) {
                int kb = ks * 8;
                uint32_t bf[4][2];
#pragma unroll
                for (int nt = 0; nt < 4; nt++) {
                    int o = nt*8 + og;
                    bf[nt][0] = sWu[(tap*32 + o)*CST + kb + kk];
                    bf[nt][1] = sWu[(tap*32 + o)*CST + kb + kk + 4];
                }
#pragma unroll
                for (int mt = 0; mt < 2; mt++) {
                    int ph = warp*2 + mt;
                    int rb = ((ph + th)*18 + tw)*CST + kb + kk;
                    uint32_t a0 = sPu[rb + pw0*CST];
                    uint32_t a1 = sPu[rb + (pw0+8)*CST];
                    uint32_t a2 = sPu[rb + pw0*CST + 4];
                    uint32_t a3 = sPu[rb + (pw0+8)*CST + 4];
#pragma unroll
                    for (int nt = 0; nt < 4; nt++)
                        MMA_TF32(acc[mt][nt], a0, a1, a2, a3,
                                 bf[nt][0], bf[nt][1]);
                }
            }
        }
    }

    __syncthreads();   // patch reads done; reuse buffer as sOut

    int m0 = warp * 32;
#pragma unroll
    for (int mt = 0; mt < 2; mt++) {
        int row0 = m0 + mt*16 + (lane >> 2);
#pragma unroll
        for (int nt = 0; nt < 4; nt++) {
            int col = nt*8 + (lane & 3)*2;
            sOut[row0*33 + col]       = fmaxf(acc[mt][nt][0] + sb2[col],   0.0f);
            sOut[row0*33 + col + 1]   = fmaxf(acc[mt][nt][1] + sb2[col+1], 0.0f);
            sOut[(row0+8)*33 + col]   = fmaxf(acc[mt][nt][2] + sb2[col],   0.0f);
            sOut[(row0+8)*33 + col+1] = fmaxf(acc[mt][nt][3] + sb2[col+1], 0.0f);
        }
    }
    __syncthreads();

    {
        int ph = tid >> 4, pw = tid & 15;
        int h = bh0 + ph, wq = bw0 + pw;
        if (h < NN && wq < NN) {
            float s = 0.0f;
#pragma unroll
            for (int o = 0; o < 32; o++) s += sOut[tid*33 + o];
            float ew = s * (1.0f / 32.0f);
            g_ahat[(size_t)b*NSQ + (size_t)wq*NN + h] = ew + (h == wq ? 1.0f : 0.0f);
            if (h == wq) {
                float* xp = g_x0 + ((size_t)b*NN + h)*32;
#pragma unroll
                for (int o = 0; o < 32; o++) xp[o] = sOut[tid*33 + o];
            }
        }
    }
}

// ---------------- degree / D^-1/2 --------------------------------------------
__global__ void deg_kernel() {
    int bt = blockIdx.x;
    const float* row = g_ahat + (size_t)bt * NN;
    int tid = threadIdx.x;
    float s = 0.0f;
    for (int i = tid; i < NN; i += 128) s += row[i];
#pragma unroll
    for (int o = 16; o > 0; o >>= 1) s += __shfl_xor_sync(0xffffffff, s, o);
    __shared__ float ws[4];
    if ((tid & 31) == 0) ws[tid >> 5] = s;
    __syncthreads();
    if (tid == 0) {
        float d = ws[0] + ws[1] + ws[2] + ws[3];
        g_dinv[bt] = d > 0.0f ? rsqrtf(d) : 0.0f;
    }
}

// ------------- XW = X @ W via tf32 MMA.  M=9408, K=FIN, N=FOUT ---------------
template<int FIN, int FOUT>
__global__ void xw_mma_kernel(const float* __restrict__ X,
                              const float* __restrict__ W,
                              float* __restrict__ XW) {
    constexpr int NT = FOUT / 8;
    int lane = threadIdx.x & 31, warp = threadIdx.x >> 5;
    int m0 = blockIdx.x * 64 + warp * 16;
    int row = lane >> 2, kq = lane & 3;

    float acc[NT][4];
#pragma unroll
    for (int nt = 0; nt < NT; nt++)
#pragma unroll
        for (int q = 0; q < 4; q++) acc[nt][q] = 0.0f;

    const float* xr0 = X + (size_t)(m0 + row) * FIN;
    const float* xr1 = X + (size_t)(m0 + row + 8) * FIN;

#pragma unroll
    for (int ks = 0; ks < FIN/8; ks++) {
        int k0 = ks*8;
        uint32_t a0 = f2tf32(__ldg(xr0 + k0 + kq));
        uint32_t a1 = f2tf32(__ldg(xr1 + k0 + kq));
        uint32_t a2 = f2tf32(__ldg(xr0 + k0 + kq + 4));
        uint32_t a3 = f2tf32(__ldg(xr1 + k0 + kq + 4));
#pragma unroll
        for (int nt = 0; nt < NT; nt++) {
            int n = nt*8 + row;
            uint32_t b0 = f2tf32(__ldg(W + (size_t)(k0 + kq)*FOUT + n));
            uint32_t b1 = f2tf32(__ldg(W + (size_t)(k0 + kq + 4)*FOUT + n));
            MMA_TF32(acc[nt], a0, a1, a2, a3, b0, b1);
        }
    }

#pragma unroll
    for (int nt = 0; nt < NT; nt++) {
        int col = nt*8 + (lane & 3)*2;
        float2* p0 = (float2*)(XW + (size_t)(m0 + row)     * FOUT + col);
        float2* p1 = (float2*)(XW + (size_t)(m0 + row + 8) * FOUT + col);
        *p0 = make_float2(acc[nt][0], acc[nt][1]);
        *p1 = make_float2(acc[nt][2], acc[nt][3]);
    }
}

// ---- Y = relu( (dinv A_hat dinv) @ XW + b ) via tf32 MMA --------------------
#define AST 156
template<int FOUT>
__global__ void agg_mma_kernel(const float* __restrict__ XW,
                               const float* __restrict__ bias,
                               float* __restrict__ Y) {
    constexpr int NTW = FOUT / 32;
    __shared__ uint32_t sA[16 * AST];
    __shared__ float sds[160];

    int tid = threadIdx.x;
    int lane = tid & 31, warp = tid >> 5;
    int b = blockIdx.y, t0 = blockIdx.x * 16;

    for (int i = tid; i < 160; i += 128)
        sds[i] = (i < NN) ? g_dinv[b*NN + i] : 0.0f;
    __syncthreads();

    const float* ab = g_ahat + (size_t)b * NSQ;
    for (int i = tid; i < 16*AST; i += 128) {
        int r = i / AST, s = i - r*AST;
        int t = t0 + r;
        float v = 0.0f;
        if (t < NN && s < NN) v = ab[(size_t)t*NN + s] * sds[t] * sds[s];
        sA[i] = f2tf32(v);
    }
    __syncthreads();

    float acc[NTW][4];
#pragma unroll
    for (int nt = 0; nt < NTW; nt++)
#pragma unroll
        for (int q = 0; q < 4; q++) acc[nt][q] = 0.0f;

    int row = lane >> 2, kq = lane & 3;
    int wn0 = warp * (FOUT/4);
    const float* xwb = XW + (size_t)b * NN * FOUT;

#pragma unroll
    for (int ks = 0; ks < 19; ks++) {
        int k0 = ks*8;
        uint32_t a0 = sA[row*AST + k0 + kq];
        uint32_t a1 = sA[(row+8)*AST + k0 + kq];
        uint32_t a2 = sA[row*AST + k0 + kq + 4];
        uint32_t a3 = sA[(row+8)*AST + k0 + kq + 4];
#pragma unroll
        for (int nt = 0; nt < NTW; nt++) {
            int n = wn0 + nt*8 + row;
            uint32_t b0 = f2tf32(__ldg(xwb + (size_t)(k0 + kq)*FOUT + n));
            uint32_t b1 = f2tf32(__ldg(xwb + (size_t)(k0 + kq + 4)*FOUT + n));
            MMA_TF32(acc[nt], a0, a1, a2, a3, b0, b1);
        }
    }

    int r0 = t0 + row, r1 = t0 + row + 8;
#pragma unroll
    for (int nt = 0; nt < NTW; nt++) {
        int col = wn0 + nt*8 + (lane & 3)*2;
        float bv0 = __ldg(bias + col), bv1 = __ldg(bias + col + 1);
        if (r0 < NN) {
            float2* p = (float2*)(Y + (size_t)(b*NN + r0)*FOUT + col);
            *p = make_float2(fmaxf(acc[nt][0] + bv0, 0.0f),
                             fmaxf(acc[nt][1] + bv1, 0.0f));
        }
        if (r1 < NN) {
            float2* p = (float2*)(Y + (size_t)(b*NN + r1)*FOUT + col);
            *p = make_float2(fmaxf(acc[nt][2] + bv0, 0.0f),
                             fmaxf(acc[nt][3] + bv1, 0.0f));
        }
    }
}

// ---------------- mean pool + policy head ------------------------------------
__global__ void head_kernel(const float* __restrict__ Y,
                            const float* __restrict__ pw,
                            const float* __restrict__ pb,
                            float* __restrict__ out) {
    int b = blockIdx.x;
    __shared__ float sp[128];
    int f = threadIdx.x;
    float s = 0.0f;
    const float* yb = Y + (size_t)b*NN*128;
    for (int n = 0; n < NN; n++) s += yb[n*128 + f];
    sp[f] = s * (1.0f / NN);
    __syncthreads();
    if (f < 5) {
        float a = pb[f];
#pragma unroll
        for (int i = 0; i < 128; i++) a += sp[i] * pw[i*5 + f];
        out[b*5 + f] = a;
    }
}

// ---------------- launch -----------------------------------------------------
extern "C" void kernel_launch(void* const* d_in, const int* in_sizes, int n_in,
                              void* d_out, int out_size) {
    const float* obs      = (const float*)d_in[0];
    const float* conv1_w  = (const float*)d_in[1];
    const float* conv1_b  = (const float*)d_in[2];
    const float* conv2_w  = (const float*)d_in[3];
    const float* conv2_b  = (const float*)d_in[4];
    const float* gcn1_w   = (const float*)d_in[5];
    const float* gcn1_b   = (const float*)d_in[6];
    const float* gcn2_w   = (const float*)d_in[7];
    const float* gcn2_b   = (const float*)d_in[8];
    const float* gcn3_w   = (const float*)d_in[9];
    const float* gcn3_b   = (const float*)d_in[10];
    const float* policy_w = (const float*)d_in[11];
    const float* policy_b = (const float*)d_in[12];
    float* out = (float*)d_out;

    float *x0, *xw, *fa, *fb;
    cudaGetSymbolAddress((void**)&x0, g_x0);
    cudaGetSymbolAddress((void**)&xw, g_xw);
    cudaGetSymbolAddress((void**)&fa, g_fa);
    cudaGetSymbolAddress((void**)&fb, g_fb);

    prep_kernel<<<23, 256>>>(conv1_w, conv2_w);
    conv_fused_kernel<<<dim3(10, 19, BB), 128>>>(obs, conv1_b, conv2_b);
    deg_kernel<<<BB*NN, 128>>>();

    xw_mma_kernel<32, 64><<<147, 128>>>(x0, gcn1_w, xw);
    agg_mma_kernel<64><<<dim3(10, BB), 128>>>(xw, gcn1_b, fa);

    xw_mma_kernel<64, 128><<<147, 128>>>(fa, gcn2_w, xw);
    agg_mma_kernel<128><<<dim3(10, BB), 128>>>(xw, gcn2_b, fb);

    xw_mma_kernel<128, 128><<<147, 128>>>(fb, gcn3_w, xw);
    agg_mma_kernel<128><<<dim3(10, BB), 128>>>(xw, gcn3_b, fa);

    head_kernel<<<BB, 128>>>(fa, policy_w, policy_b, out);
}